// round 11
// baseline (speedup 1.0000x reference)
#include <cuda_runtime.h>
#include <cuda_fp16.h>
#include <cstdint>

#define HW     9216
#define IMG_W  96
#define IMG_H  96
#define CCH    192
#define NB     4

// Scratch (no cudaMalloc allowed)
__device__ __half g_x16[(size_t)NB * HW * CCH];          // [b][pix][192] fp16
__device__ __half g_w16[(576 + 192) * CCH];              // w_qkv then w_out, fp16
__device__ __half g_q  [(size_t)NB * HW * CCH];          // [b][24 pg][HW][8] fp16 (pre-scaled by scale/ln2)
__device__ __half g_k  [(size_t)NB * HW * CCH];          // [b][24 pg][HW][8] fp16
__device__ __half g_v  [(size_t)NB * HW * CCH];          // [b][24 pg][HW][8] fp16
__device__ __half g_at [(size_t)NB * HW * CCH];          // [b][pix][192] fp16

// ============================================================================
// Weight prep: fp32 -> fp16
// ============================================================================
__global__ void prep_weights(const float* __restrict__ w_qkv,
                             const float* __restrict__ w_out) {
    const int i = blockIdx.x * 256 + threadIdx.x;
    const int total = (576 + 192) * CCH;
    if (i >= total) return;
    const float v = (i < 576 * CCH) ? w_qkv[i] : w_out[i - 576 * CCH];
    g_w16[i] = __float2half_rn(v);
}

// ============================================================================
// Transpose: x[b][192][HW] fp32 -> g_x16[b][pix][192] fp16
// ============================================================================
__global__ void transpose_k(const float* __restrict__ x) {
    __shared__ float tile[32][33];
    const int b  = blockIdx.z;
    const int p0 = blockIdx.x * 32, c0 = blockIdx.y * 32;
    const float* xb = x + (size_t)b * CCH * HW;
    __half* tb = g_x16 + (size_t)b * HW * CCH;
    const int tx = threadIdx.x, ty = threadIdx.y;
    #pragma unroll
    for (int j = 0; j < 32; j += 8)
        tile[ty + j][tx] = xb[(size_t)(c0 + ty + j) * HW + p0 + tx];
    __syncthreads();
    #pragma unroll
    for (int j = 0; j < 32; j += 8)
        tb[(size_t)(p0 + ty + j) * CCH + c0 + tx] = __float2half_rn(tile[tx][ty + j]);
}

// ============================================================================
// fp16 GEMM via mma.sync.m16n8k16 with register double-buffered K stages.
//   Tile M=128, N=64, K staged 3x64, 8 warps, warp tile 32x32.
//   MODE=1: C fp32 [n][HW] channel-major (d_out).
//   MODE=2: qkv epilogue -> g_q/g_k/g_v fp16 d8-packed (q pre-scaled).
// ============================================================================
#define RS    144                      // smem tile row stride bytes
#define SM_A  0
#define SM_B  (128 * RS)               // 18432
#define SM_GTOT (SM_B + 64 * RS)       // 27648 (>= 128*144 staging)

// q pre-scale: (1/sqrt(32)) / ln(2)  -> lets natt use exp2f directly
#define QSCALE 0.2550868054849892f
#define INV_LN2 1.4426950408889634f

__device__ __forceinline__ void mma16816(float* c, const uint32_t* a, const uint32_t* b) {
    asm volatile(
        "mma.sync.aligned.m16n8k16.row.col.f32.f16.f16.f32 "
        "{%0,%1,%2,%3}, {%4,%5,%6,%7}, {%8,%9}, {%0,%1,%2,%3};"
        : "+f"(c[0]), "+f"(c[1]), "+f"(c[2]), "+f"(c[3])
        : "r"(a[0]), "r"(a[1]), "r"(a[2]), "r"(a[3]), "r"(b[0]), "r"(b[1]));
}

template<int MODE>
__global__ __launch_bounds__(256, 2)
void mma_gemm(const __half* __restrict__ A, const __half* __restrict__ B,
              float* __restrict__ Cout)
{
    extern __shared__ char smem[];
    const int t    = threadIdx.x;
    const int wid  = t >> 5, lane = t & 31;
    const int gid  = lane >> 2, tig = lane & 3;
    const int wm   = wid & 3, wn = wid >> 2;
    const int m0   = blockIdx.y * 128;
    const int n0   = blockIdx.x * 64;
    const int b    = blockIdx.z;

    const __half* Ab = A + (size_t)b * HW * CCH + (size_t)m0 * CCH;

    float acc[2][4][4];
    #pragma unroll
    for (int mi = 0; mi < 2; mi++)
        #pragma unroll
        for (int ni = 0; ni < 4; ni++)
            #pragma unroll
            for (int j = 0; j < 4; j++) acc[mi][ni][j] = 0.f;

    const int lrow = t >> 3, lc8 = (t & 7) * 8;      // loader coords

    // prefetch stage 0 into registers
    uint4 pa[4], pb[2];
    #pragma unroll
    for (int i = 0; i < 4; i++) {
        const int row = lrow + i * 32;
        pa[i] = *(const uint4*)(Ab + (size_t)row * CCH + lc8);
    }
    #pragma unroll
    for (int i = 0; i < 2; i++) {
        const int row = lrow + i * 32;
        pb[i] = *(const uint4*)(B + (size_t)(n0 + row) * CCH + lc8);
    }

    #pragma unroll 1
    for (int s = 0; s < 3; s++) {
        // store staged regs to smem
        #pragma unroll
        for (int i = 0; i < 4; i++)
            *(uint4*)(smem + SM_A + (lrow + i * 32) * RS + lc8 * 2) = pa[i];
        #pragma unroll
        for (int i = 0; i < 2; i++)
            *(uint4*)(smem + SM_B + (lrow + i * 32) * RS + lc8 * 2) = pb[i];
        __syncthreads();

        // issue next-stage global loads (overlap with mma below)
        if (s < 2) {
            const int k0 = (s + 1) * 64;
            #pragma unroll
            for (int i = 0; i < 4; i++) {
                const int row = lrow + i * 32;
                pa[i] = *(const uint4*)(Ab + (size_t)row * CCH + k0 + lc8);
            }
            #pragma unroll
            for (int i = 0; i < 2; i++) {
                const int row = lrow + i * 32;
                pb[i] = *(const uint4*)(B + (size_t)(n0 + row) * CCH + k0 + lc8);
            }
        }

        #pragma unroll
        for (int kk = 0; kk < 4; kk++) {
            const uint32_t cb = kk * 32 + tig * 4;
            uint32_t ah[2][4], bh[4][2];
            #pragma unroll
            for (int mi = 0; mi < 2; mi++) {
                const uint32_t r0 = (wm * 32 + mi * 16 + gid) * RS + cb;
                ah[mi][0] = *(const uint32_t*)(smem + SM_A + r0);
                ah[mi][1] = *(const uint32_t*)(smem + SM_A + r0 + 8 * RS);
                ah[mi][2] = *(const uint32_t*)(smem + SM_A + r0 + 16);
                ah[mi][3] = *(const uint32_t*)(smem + SM_A + r0 + 8 * RS + 16);
            }
            #pragma unroll
            for (int ni = 0; ni < 4; ni++) {
                const uint32_t rn = (wn * 32 + ni * 8 + gid) * RS + cb;
                bh[ni][0] = *(const uint32_t*)(smem + SM_B + rn);
                bh[ni][1] = *(const uint32_t*)(smem + SM_B + rn + 16);
            }
            #pragma unroll
            for (int mi = 0; mi < 2; mi++)
                #pragma unroll
                for (int ni = 0; ni < 4; ni++)
                    mma16816(acc[mi][ni], ah[mi], bh[ni]);
        }
        __syncthreads();
    }

    if (MODE == 1) {
        float* Cb = Cout + (size_t)b * CCH * HW;
        #pragma unroll
        for (int mi = 0; mi < 2; mi++) {
            const int row = m0 + wm * 32 + mi * 16 + gid;
            #pragma unroll
            for (int ni = 0; ni < 4; ni++) {
                const int col = n0 + wn * 32 + ni * 8 + 2 * tig;
                Cb[(size_t)col       * HW + row]     = acc[mi][ni][0];
                Cb[(size_t)(col + 1) * HW + row]     = acc[mi][ni][1];
                Cb[(size_t)col       * HW + row + 8] = acc[mi][ni][2];
                Cb[(size_t)(col + 1) * HW + row + 8] = acc[mi][ni][3];
            }
        }
    } else {
        // unified qkv epilogue: fp16 d8-packed via smem staging.
        const int type = n0 / 192;             // 0=q, 1=k, 2=v
        const float sc = (type == 0) ? QSCALE : 1.0f;
        __half* st = (__half*)smem;            // stride 72 halves (144B)
        #pragma unroll
        for (int mi = 0; mi < 2; mi++) {
            const int rl = wm * 32 + mi * 16 + gid;
            #pragma unroll
            for (int ni = 0; ni < 4; ni++) {
                const int cl = wn * 32 + ni * 8 + 2 * tig;
                *(__half2*)&st[rl * 72 + cl] =
                    __floats2half2_rn(acc[mi][ni][0] * sc, acc[mi][ni][1] * sc);
                *(__half2*)&st[(rl + 8) * 72 + cl] =
                    __floats2half2_rn(acc[mi][ni][2] * sc, acc[mi][ni][3] * sc);
            }
        }
        __syncthreads();
        __half* dst = (type == 0) ? g_q : (type == 1) ? g_k : g_v;
        const int pgb = (n0 - type * 192) / 8;
        #pragma unroll
        for (int i = 0; i < 4; i++) {          // 8 pgs x 128 rows
            const int idx = i * 256 + t;
            const int r = idx & 127, pg = idx >> 7;
            uint4 val = *(uint4*)&st[r * 72 + pg * 8];
            *(uint4*)&dst[(((size_t)b * 24 + pgb + pg) * HW + m0 + r) * 8] = val;
        }
    }
}

// ============================================================================
// Neighborhood attention: q/k/v fp16 d8-packed; q pre-scaled by scale/ln2.
// BND=false: interior blocks, no bounds logic at all.
// BND=true : clamped (always-valid) loads + predicated contribution — loads
//            are unguarded so ptxas can batch them (high MLP).
// ============================================================================
template<int K, int DIL, bool BND>
__device__ __forceinline__ void natt_core(const float* __restrict__ sbias,
                                          int head, int b)
{
    const int w   = blockIdx.x * 32 + threadIdx.x;
    const int h   = blockIdx.y * 4  + threadIdx.y;
    const int pix = h * IMG_W + w;

    const __half* qp = g_q + (((size_t)b * 24 + head * 4) * HW + pix) * 8;
    const __half* kb = g_k + ((size_t)b * 24 + head * 4) * HW * 8;
    const __half* vb = g_v + ((size_t)b * 24 + head * 4) * HW * 8;

    __half2 qh[16];
    #pragma unroll
    for (int j = 0; j < 4; j++) {
        uint4 r = *(const uint4*)(qp + (size_t)j * HW * 8);
        qh[4 * j + 0] = *(const __half2*)&r.x;
        qh[4 * j + 1] = *(const __half2*)&r.y;
        qh[4 * j + 2] = *(const __half2*)&r.z;
        qh[4 * j + 3] = *(const __half2*)&r.w;
    }

    float4 acc[8];
    #pragma unroll
    for (int i = 0; i < 8; i++) acc[i] = make_float4(0.f, 0.f, 0.f, 0.f);
    float l = 0.f;

    #pragma unroll 1
    for (int di = 0; di < K; di++) {
        const int hh = h + (di - K / 2) * DIL;
        const int hc = BND ? min(max(hh, 0), IMG_H - 1) : hh;
        const bool rok = BND ? ((unsigned)hh < IMG_H) : true;
        #pragma unroll
        for (int dj = 0; dj < K; dj++) {
            const int ww = w + (dj - K / 2) * DIL;
            const int wc = BND ? min(max(ww, 0), IMG_W - 1) : ww;
            const bool ok = BND ? (rok && ((unsigned)ww < IMG_W)) : true;
            const int off = hc * IMG_W + wc;

            // unconditional (always-valid) k load + HFMA2 dot
            const __half* kp = kb + (size_t)off * 8;
            __half2 s0 = __float2half2_rn(0.f);
            __half2 s1 = __float2half2_rn(0.f);
            #pragma unroll
            for (int j = 0; j < 4; j++) {
                uint4 raw = *(const uint4*)(kp + (size_t)j * HW * 8);
                s0 = __hfma2(qh[4 * j + 0], *(const __half2*)&raw.x, s0);
                s1 = __hfma2(qh[4 * j + 1], *(const __half2*)&raw.y, s1);
                s0 = __hfma2(qh[4 * j + 2], *(const __half2*)&raw.z, s0);
                s1 = __hfma2(qh[4 * j + 3], *(const __half2*)&raw.w, s1);
            }
            const float2 sf = __half22float2(__hadd2(s0, s1));
            const float s = sf.x + sf.y;

            const float bias = sbias[di * K + dj];
            const float e = exp2f(BND ? (ok ? s + bias : bias) : (s + bias));
            l += e;
            const float ev = BND ? (ok ? e : 0.f) : e;

            const __half* vp = vb + (size_t)off * 8;
            #pragma unroll
            for (int j = 0; j < 4; j++) {
                uint4 raw = *(const uint4*)(vp + (size_t)j * HW * 8);
                float2 p0 = __half22float2(*(const __half2*)&raw.x);
                float2 p1 = __half22float2(*(const __half2*)&raw.y);
                float2 p2 = __half22float2(*(const __half2*)&raw.z);
                float2 p3 = __half22float2(*(const __half2*)&raw.w);
                acc[2*j].x   += ev * p0.x; acc[2*j].y   += ev * p0.y;
                acc[2*j].z   += ev * p1.x; acc[2*j].w   += ev * p1.y;
                acc[2*j+1].x += ev * p2.x; acc[2*j+1].y += ev * p2.y;
                acc[2*j+1].z += ev * p3.x; acc[2*j+1].w += ev * p3.y;
            }
        }
    }

    const float il = 1.f / l;
    const size_t ob = ((size_t)b * HW + pix) * CCH + head * 32;
    #pragma unroll
    for (int j = 0; j < 4; j++) {
        __half2 h0 = __floats2half2_rn(acc[2*j].x   * il, acc[2*j].y   * il);
        __half2 h1 = __floats2half2_rn(acc[2*j].z   * il, acc[2*j].w   * il);
        __half2 h2 = __floats2half2_rn(acc[2*j+1].x * il, acc[2*j+1].y * il);
        __half2 h3 = __floats2half2_rn(acc[2*j+1].z * il, acc[2*j+1].w * il);
        uint4 val;
        val.x = *(uint32_t*)&h0; val.y = *(uint32_t*)&h1;
        val.z = *(uint32_t*)&h2; val.w = *(uint32_t*)&h3;
        *(uint4*)&g_at[ob + j * 8] = val;
    }
}

template<int K, int DIL>
__device__ __forceinline__ void natt_body(const float* __restrict__ sbias,
                                          int head, int b)
{
    const int r   = DIL * (K / 2);
    const int wlo = blockIdx.x * 32, hlo = blockIdx.y * 4;
    const bool interior = (wlo >= r) && (wlo + 32 + r <= IMG_W)
                       && (hlo >= r) && (hlo + 4 + r <= IMG_H);
    if (interior) natt_core<K, DIL, false>(sbias, head, b);
    else          natt_core<K, DIL, true >(sbias, head, b);
}

__global__ __launch_bounds__(128, 7)
void natt_all(const float* __restrict__ b0, const float* __restrict__ b1,
              const float* __restrict__ b2, const float* __restrict__ b3,
              const float* __restrict__ b4, const float* __restrict__ b5)
{
    __shared__ float sb[81];
    // Heavy heads first: tail of the grid is cheap CTAs.
    const int HORD[6] = {4, 5, 3, 2, 1, 0};
    const int z = blockIdx.z;
    const int head = HORD[z >> 2];
    const int b    = z & 3;
    const float* bp;
    int k2;
    switch (head) {
        case 0: bp = b0; k2 = 9;  break;
        case 1: bp = b1; k2 = 25; break;
        case 2: bp = b2; k2 = 49; break;
        case 3: bp = b3; k2 = 49; break;
        case 4: bp = b4; k2 = 81; break;
        default: bp = b5; k2 = 81; break;
    }
    const int t = threadIdx.y * 32 + threadIdx.x;
    if (t < k2) sb[t] = bp[t] * INV_LN2;     // bias in log2 domain
    __syncthreads();
    switch (head) {
        case 0: natt_body<3, 1>(sb, 0, b); break;
        case 1: natt_body<5, 2>(sb, 1, b); break;
        case 2: natt_body<7, 1>(sb, 2, b); break;
        case 3: natt_body<7, 3>(sb, 3, b); break;
        case 4: natt_body<9, 1>(sb, 4, b); break;
        case 5: natt_body<9, 2>(sb, 5, b); break;
    }
}

// ============================================================================
extern "C" void kernel_launch(void* const* d_in, const int* in_sizes, int n_in,
                              void* d_out, int out_size)
{
    (void)in_sizes; (void)n_in; (void)out_size;
    const float* x     = (const float*)d_in[0];
    const float* w_qkv = (const float*)d_in[1];
    const float* w_out = (const float*)d_in[2];
    const float* b0 = (const float*)d_in[3];
    const float* b1 = (const float*)d_in[4];
    const float* b2 = (const float*)d_in[5];
    const float* b3 = (const float*)d_in[6];
    const float* b4 = (const float*)d_in[7];
    const float* b5 = (const float*)d_in[8];

    __half *x16, *w16, *at16;
    cudaGetSymbolAddress((void**)&x16,  g_x16);
    cudaGetSymbolAddress((void**)&w16,  g_w16);
    cudaGetSymbolAddress((void**)&at16, g_at);

    cudaFuncSetAttribute(mma_gemm<1>, cudaFuncAttributeMaxDynamicSharedMemorySize, SM_GTOT);
    cudaFuncSetAttribute(mma_gemm<2>, cudaFuncAttributeMaxDynamicSharedMemorySize, SM_GTOT);

    prep_weights<<<(768 * CCH + 255) / 256, 256>>>(w_qkv, w_out);
    transpose_k<<<dim3(HW / 32, CCH / 32, NB), dim3(32, 8)>>>(x);

    // qkv = x16 @ w_qkv^T  -> g_q / g_k / g_v (fp16 d8-packed, q pre-scaled)
    mma_gemm<2><<<dim3(576 / 64, HW / 128, NB), 256, SM_GTOT>>>(x16, w16, nullptr);

    natt_all<<<dim3(IMG_W / 32, IMG_H / 4, NB * 6), dim3(32, 4)>>>(
        b0, b1, b2, b3, b4, b5);

    // d_out[b][ch][pix] = (attn @ w_out^T)^T
    mma_gemm<1><<<dim3(CCH / 64, HW / 128, NB), 256, SM_GTOT>>>(
        at16, w16 + 576 * CCH, (float*)d_out);
}

// round 12
// speedup vs baseline: 1.2474x; 1.2474x over previous
#include <cuda_runtime.h>
#include <cuda_fp16.h>
#include <cstdint>

#define HW     9216
#define IMG_W  96
#define IMG_H  96
#define CCH    192
#define NB     4

// Scratch (no cudaMalloc allowed)
__device__ __half g_x16[(size_t)NB * HW * CCH];          // [b][pix][192] fp16
__device__ __half g_w16[(576 + 192) * CCH];              // w_qkv then w_out, fp16
__device__ __half g_q  [(size_t)NB * HW * CCH];          // [b][24 pg][HW][8] fp16 (pre-scaled by scale/ln2)
__device__ __half g_k  [(size_t)NB * HW * CCH];          // [b][24 pg][HW][8] fp16
__device__ __half g_v  [(size_t)NB * HW * CCH];          // [b][24 pg][HW][8] fp16
__device__ __half g_at [(size_t)NB * HW * CCH];          // [b][pix][192] fp16

// q pre-scale: (1/sqrt(32)) / ln(2)  -> natt uses exp2f directly
#define QSCALE 0.2550868054849892f
#define INV_LN2 1.4426950408889634f

// ============================================================================
// Weight prep: fp32 -> fp16
// ============================================================================
__global__ void prep_weights(const float* __restrict__ w_qkv,
                             const float* __restrict__ w_out) {
    const int i = blockIdx.x * 256 + threadIdx.x;
    const int total = (576 + 192) * CCH;
    if (i >= total) return;
    const float v = (i < 576 * CCH) ? w_qkv[i] : w_out[i - 576 * CCH];
    g_w16[i] = __float2half_rn(v);
}

// ============================================================================
// Transpose: x[b][192][HW] fp32 -> g_x16[b][pix][192] fp16
// ============================================================================
__global__ void transpose_k(const float* __restrict__ x) {
    __shared__ float tile[32][33];
    const int b  = blockIdx.z;
    const int p0 = blockIdx.x * 32, c0 = blockIdx.y * 32;
    const float* xb = x + (size_t)b * CCH * HW;
    __half* tb = g_x16 + (size_t)b * HW * CCH;
    const int tx = threadIdx.x, ty = threadIdx.y;
    #pragma unroll
    for (int j = 0; j < 32; j += 8)
        tile[ty + j][tx] = xb[(size_t)(c0 + ty + j) * HW + p0 + tx];
    __syncthreads();
    #pragma unroll
    for (int j = 0; j < 32; j += 8)
        tb[(size_t)(p0 + ty + j) * CCH + c0 + tx] = __float2half_rn(tile[tx][ty + j]);
}

// ============================================================================
// fp16 GEMM via mma.sync.m16n8k16 (R10 proven loader, no reg double-buffer).
//   Tile M=128, N=64, K staged 3x64, 8 warps, warp tile 32x32.
//   MODE=1: C fp32 [n][HW] channel-major (d_out).
//   MODE=2: qkv epilogue -> g_q/g_k/g_v fp16 d8-packed (q pre-scaled).
// ============================================================================
#define RS    144                      // smem tile row stride bytes
#define SM_A  0
#define SM_B  (128 * RS)               // 18432
#define SM_GTOT (SM_B + 64 * RS)       // 27648 (>= 128*144 staging)

__device__ __forceinline__ void mma16816(float* c, const uint32_t* a, const uint32_t* b) {
    asm volatile(
        "mma.sync.aligned.m16n8k16.row.col.f32.f16.f16.f32 "
        "{%0,%1,%2,%3}, {%4,%5,%6,%7}, {%8,%9}, {%0,%1,%2,%3};"
        : "+f"(c[0]), "+f"(c[1]), "+f"(c[2]), "+f"(c[3])
        : "r"(a[0]), "r"(a[1]), "r"(a[2]), "r"(a[3]), "r"(b[0]), "r"(b[1]));
}

template<int MODE>
__global__ __launch_bounds__(256, 2)
void mma_gemm(const __half* __restrict__ A, const __half* __restrict__ B,
              float* __restrict__ Cout)
{
    extern __shared__ char smem[];
    const int t    = threadIdx.x;
    const int wid  = t >> 5, lane = t & 31;
    const int gid  = lane >> 2, tig = lane & 3;
    const int wm   = wid & 3, wn = wid >> 2;
    const int m0   = blockIdx.y * 128;
    const int n0   = blockIdx.x * 64;
    const int b    = blockIdx.z;

    const __half* Ab = A + (size_t)b * HW * CCH + (size_t)m0 * CCH;

    float acc[2][4][4];
    #pragma unroll
    for (int mi = 0; mi < 2; mi++)
        #pragma unroll
        for (int ni = 0; ni < 4; ni++)
            #pragma unroll
            for (int j = 0; j < 4; j++) acc[mi][ni][j] = 0.f;

    #pragma unroll 1
    for (int s = 0; s < 3; s++) {
        const int k0 = s * 64;
        #pragma unroll
        for (int i = 0; i < 4; i++) {       // A: 128x64 fp16 = 1024 16B chunks
            const int idx = t + i * 256;
            const int row = idx >> 3, c8 = (idx & 7) * 8;
            *(uint4*)(smem + SM_A + row * RS + c8 * 2) =
                *(const uint4*)(Ab + (size_t)row * CCH + k0 + c8);
        }
        #pragma unroll
        for (int i = 0; i < 2; i++) {       // B: 64x64 fp16 = 512 chunks
            const int idx = t + i * 256;
            const int row = idx >> 3, c8 = (idx & 7) * 8;
            *(uint4*)(smem + SM_B + row * RS + c8 * 2) =
                *(const uint4*)(B + (size_t)(n0 + row) * CCH + k0 + c8);
        }
        __syncthreads();

        #pragma unroll
        for (int kk = 0; kk < 4; kk++) {
            const uint32_t cb = kk * 32 + tig * 4;
            uint32_t ah[2][4], bh[4][2];
            #pragma unroll
            for (int mi = 0; mi < 2; mi++) {
                const uint32_t r0 = (wm * 32 + mi * 16 + gid) * RS + cb;
                ah[mi][0] = *(const uint32_t*)(smem + SM_A + r0);
                ah[mi][1] = *(const uint32_t*)(smem + SM_A + r0 + 8 * RS);
                ah[mi][2] = *(const uint32_t*)(smem + SM_A + r0 + 16);
                ah[mi][3] = *(const uint32_t*)(smem + SM_A + r0 + 8 * RS + 16);
            }
            #pragma unroll
            for (int ni = 0; ni < 4; ni++) {
                const uint32_t rn = (wn * 32 + ni * 8 + gid) * RS + cb;
                bh[ni][0] = *(const uint32_t*)(smem + SM_B + rn);
                bh[ni][1] = *(const uint32_t*)(smem + SM_B + rn + 16);
            }
            #pragma unroll
            for (int mi = 0; mi < 2; mi++)
                #pragma unroll
                for (int ni = 0; ni < 4; ni++)
                    mma16816(acc[mi][ni], ah[mi], bh[ni]);
        }
        __syncthreads();
    }

    if (MODE == 1) {
        float* Cb = Cout + (size_t)b * CCH * HW;
        #pragma unroll
        for (int mi = 0; mi < 2; mi++) {
            const int row = m0 + wm * 32 + mi * 16 + gid;
            #pragma unroll
            for (int ni = 0; ni < 4; ni++) {
                const int col = n0 + wn * 32 + ni * 8 + 2 * tig;
                Cb[(size_t)col       * HW + row]     = acc[mi][ni][0];
                Cb[(size_t)(col + 1) * HW + row]     = acc[mi][ni][1];
                Cb[(size_t)col       * HW + row + 8] = acc[mi][ni][2];
                Cb[(size_t)(col + 1) * HW + row + 8] = acc[mi][ni][3];
            }
        }
    } else {
        // unified qkv epilogue: fp16 d8-packed via smem staging.
        const int type = n0 / 192;             // 0=q, 1=k, 2=v
        const float sc = (type == 0) ? QSCALE : 1.0f;
        __half* st = (__half*)smem;            // stride 72 halves (144B)
        #pragma unroll
        for (int mi = 0; mi < 2; mi++) {
            const int rl = wm * 32 + mi * 16 + gid;
            #pragma unroll
            for (int ni = 0; ni < 4; ni++) {
                const int cl = wn * 32 + ni * 8 + 2 * tig;
                *(__half2*)&st[rl * 72 + cl] =
                    __floats2half2_rn(acc[mi][ni][0] * sc, acc[mi][ni][1] * sc);
                *(__half2*)&st[(rl + 8) * 72 + cl] =
                    __floats2half2_rn(acc[mi][ni][2] * sc, acc[mi][ni][3] * sc);
            }
        }
        __syncthreads();
        __half* dst = (type == 0) ? g_q : (type == 1) ? g_k : g_v;
        const int pgb = (n0 - type * 192) / 8;
        #pragma unroll
        for (int i = 0; i < 4; i++) {          // 8 pgs x 128 rows
            const int idx = i * 256 + t;
            const int r = idx & 127, pg = idx >> 7;
            uint4 val = *(uint4*)&st[r * 72 + pg * 8];
            *(uint4*)&dst[(((size_t)b * 24 + pgb + pg) * HW + m0 + r) * 8] = val;
        }
    }
}

// ============================================================================
// Neighborhood attention (R10 guarded body + exp2 + grouped fp16 v-accum).
// Per window row: v accumulated in 16 half2 HFMA2 regs, promoted to fp32
// once per row (<=9 fp16 adds per chain; overflow-safe, err ~2-3e-4).
// ============================================================================
template<int K, int DIL>
__device__ __forceinline__ void natt_body(const float* __restrict__ sbias,
                                          int head, int b)
{
    const int w   = blockIdx.x * 32 + threadIdx.x;
    const int h   = blockIdx.y * 4  + threadIdx.y;
    const int pix = h * IMG_W + w;

    const __half* qp = g_q + (((size_t)b * 24 + head * 4) * HW + pix) * 8;
    const __half* kb = g_k + ((size_t)b * 24 + head * 4) * HW * 8;
    const __half* vb = g_v + ((size_t)b * 24 + head * 4) * HW * 8;

    __half2 qh[16];
    #pragma unroll
    for (int j = 0; j < 4; j++) {
        uint4 r = *(const uint4*)(qp + (size_t)j * HW * 8);
        qh[4 * j + 0] = *(const __half2*)&r.x;
        qh[4 * j + 1] = *(const __half2*)&r.y;
        qh[4 * j + 2] = *(const __half2*)&r.z;
        qh[4 * j + 3] = *(const __half2*)&r.w;
    }

    float4 acc[8];
    #pragma unroll
    for (int i = 0; i < 8; i++) acc[i] = make_float4(0.f, 0.f, 0.f, 0.f);
    float l = 0.f;

    #pragma unroll 1
    for (int di = 0; di < K; di++) {
        const int hh = h + (di - K / 2) * DIL;
        const bool rok = ((unsigned)hh < IMG_H);

        // per-row fp16 v accumulators
        __half2 a16[16];
        #pragma unroll
        for (int i = 0; i < 16; i++) a16[i] = __float2half2_rn(0.f);

        #pragma unroll
        for (int dj = 0; dj < K; dj++) {
            const int ww = w + (dj - K / 2) * DIL;
            const bool ok = rok && ((unsigned)ww < IMG_W);
            const int off = hh * IMG_W + ww;
            float s = 0.f;
            if (ok) {
                const __half* kp = kb + (size_t)off * 8;
                __half2 s0 = __float2half2_rn(0.f);
                __half2 s1 = __float2half2_rn(0.f);
                #pragma unroll
                for (int j = 0; j < 4; j++) {
                    uint4 raw = *(const uint4*)(kp + (size_t)j * HW * 8);
                    s0 = __hfma2(qh[4 * j + 0], *(const __half2*)&raw.x, s0);
                    s1 = __hfma2(qh[4 * j + 1], *(const __half2*)&raw.y, s1);
                    s0 = __hfma2(qh[4 * j + 2], *(const __half2*)&raw.z, s0);
                    s1 = __hfma2(qh[4 * j + 3], *(const __half2*)&raw.w, s1);
                }
                const float2 sf = __half22float2(__hadd2(s0, s1));
                s = sf.x + sf.y;
            }
            const float e = exp2f(s + sbias[di * K + dj]);
            l += e;
            if (ok) {
                const __half2 eh = __float2half2_rn(e);
                const __half* vp = vb + (size_t)off * 8;
                #pragma unroll
                for (int j = 0; j < 4; j++) {
                    uint4 raw = *(const uint4*)(vp + (size_t)j * HW * 8);
                    a16[4*j+0] = __hfma2(eh, *(const __half2*)&raw.x, a16[4*j+0]);
                    a16[4*j+1] = __hfma2(eh, *(const __half2*)&raw.y, a16[4*j+1]);
                    a16[4*j+2] = __hfma2(eh, *(const __half2*)&raw.z, a16[4*j+2]);
                    a16[4*j+3] = __hfma2(eh, *(const __half2*)&raw.w, a16[4*j+3]);
                }
            }
        }

        // promote row partials to fp32
        #pragma unroll
        for (int j = 0; j < 4; j++) {
            float2 f0 = __half22float2(a16[4*j+0]);
            float2 f1 = __half22float2(a16[4*j+1]);
            float2 f2 = __half22float2(a16[4*j+2]);
            float2 f3 = __half22float2(a16[4*j+3]);
            acc[2*j].x   += f0.x; acc[2*j].y   += f0.y;
            acc[2*j].z   += f1.x; acc[2*j].w   += f1.y;
            acc[2*j+1].x += f2.x; acc[2*j+1].y += f2.y;
            acc[2*j+1].z += f3.x; acc[2*j+1].w += f3.y;
        }
    }

    const float il = 1.f / l;
    const size_t ob = ((size_t)b * HW + pix) * CCH + head * 32;
    #pragma unroll
    for (int j = 0; j < 4; j++) {
        __half2 h0 = __floats2half2_rn(acc[2*j].x   * il, acc[2*j].y   * il);
        __half2 h1 = __floats2half2_rn(acc[2*j].z   * il, acc[2*j].w   * il);
        __half2 h2 = __floats2half2_rn(acc[2*j+1].x * il, acc[2*j+1].y * il);
        __half2 h3 = __floats2half2_rn(acc[2*j+1].z * il, acc[2*j+1].w * il);
        uint4 val;
        val.x = *(uint32_t*)&h0; val.y = *(uint32_t*)&h1;
        val.z = *(uint32_t*)&h2; val.w = *(uint32_t*)&h3;
        *(uint4*)&g_at[ob + j * 8] = val;
    }
}

__global__ __launch_bounds__(128, 6)
void natt_all(const float* __restrict__ b0, const float* __restrict__ b1,
              const float* __restrict__ b2, const float* __restrict__ b3,
              const float* __restrict__ b4, const float* __restrict__ b5)
{
    __shared__ float sb[81];
    // Heavy heads first: tail of the grid is cheap CTAs.
    const int HORD[6] = {4, 5, 3, 2, 1, 0};
    const int z = blockIdx.z;
    const int head = HORD[z >> 2];
    const int b    = z & 3;
    const float* bp;
    int k2;
    switch (head) {
        case 0: bp = b0; k2 = 9;  break;
        case 1: bp = b1; k2 = 25; break;
        case 2: bp = b2; k2 = 49; break;
        case 3: bp = b3; k2 = 49; break;
        case 4: bp = b4; k2 = 81; break;
        default: bp = b5; k2 = 81; break;
    }
    const int t = threadIdx.y * 32 + threadIdx.x;
    if (t < k2) sb[t] = bp[t] * INV_LN2;     // bias in log2 domain
    __syncthreads();
    switch (head) {
        case 0: natt_body<3, 1>(sb, 0, b); break;
        case 1: natt_body<5, 2>(sb, 1, b); break;
        case 2: natt_body<7, 1>(sb, 2, b); break;
        case 3: natt_body<7, 3>(sb, 3, b); break;
        case 4: natt_body<9, 1>(sb, 4, b); break;
        case 5: natt_body<9, 2>(sb, 5, b); break;
    }
}

// ============================================================================
extern "C" void kernel_launch(void* const* d_in, const int* in_sizes, int n_in,
                              void* d_out, int out_size)
{
    (void)in_sizes; (void)n_in; (void)out_size;
    const float* x     = (const float*)d_in[0];
    const float* w_qkv = (const float*)d_in[1];
    const float* w_out = (const float*)d_in[2];
    const float* b0 = (const float*)d_in[3];
    const float* b1 = (const float*)d_in[4];
    const float* b2 = (const float*)d_in[5];
    const float* b3 = (const float*)d_in[6];
    const float* b4 = (const float*)d_in[7];
    const float* b5 = (const float*)d_in[8];

    __half *x16, *w16, *at16;
    cudaGetSymbolAddress((void**)&x16,  g_x16);
    cudaGetSymbolAddress((void**)&w16,  g_w16);
    cudaGetSymbolAddress((void**)&at16, g_at);

    cudaFuncSetAttribute(mma_gemm<1>, cudaFuncAttributeMaxDynamicSharedMemorySize, SM_GTOT);
    cudaFuncSetAttribute(mma_gemm<2>, cudaFuncAttributeMaxDynamicSharedMemorySize, SM_GTOT);

    prep_weights<<<(768 * CCH + 255) / 256, 256>>>(w_qkv, w_out);
    transpose_k<<<dim3(HW / 32, CCH / 32, NB), dim3(32, 8)>>>(x);

    // qkv = x16 @ w_qkv^T  -> g_q / g_k / g_v (fp16 d8-packed, q pre-scaled)
    mma_gemm<2><<<dim3(576 / 64, HW / 128, NB), 256, SM_GTOT>>>(x16, w16, nullptr);

    natt_all<<<dim3(IMG_W / 32, IMG_H / 4, NB * 6), dim3(32, 4)>>>(
        b0, b1, b2, b3, b4, b5);

    // d_out[b][ch][pix] = (attn @ w_out^T)^T
    mma_gemm<1><<<dim3(CCH / 64, HW / 128, NB), 256, SM_GTOT>>>(
        at16, w16 + 576 * CCH, (float*)d_out);
}

// round 13
// speedup vs baseline: 1.2961x; 1.0390x over previous
#include <cuda_runtime.h>
#include <cuda_fp16.h>
#include <cstdint>

#define HW     9216
#define IMG_W  96
#define IMG_H  96
#define CCH    192
#define NB     4

// Scratch (no cudaMalloc allowed)
__device__ __half g_x16[(size_t)NB * HW * CCH];          // [b][pix][192] fp16
__device__ __half g_w16[(576 + 192) * CCH];              // w_qkv then w_out, fp16
__device__ __half g_q  [(size_t)NB * HW * CCH];          // [b][24 pg][HW][8] fp16 (pre-scaled by scale/ln2)
__device__ __half g_k  [(size_t)NB * HW * CCH];          // [b][24 pg][HW][8] fp16
__device__ __half g_v  [(size_t)NB * HW * CCH];          // [b][24 pg][HW][8] fp16
__device__ __half g_at [(size_t)NB * HW * CCH];          // [b][pix][192] fp16

// q pre-scale: (1/sqrt(32)) / ln(2)  -> natt uses exp2f directly
#define QSCALE 0.2550868054849892f
#define INV_LN2 1.4426950408889634f

// ============================================================================
// Weight prep: fp32 -> fp16
// ============================================================================
__global__ void prep_weights(const float* __restrict__ w_qkv,
                             const float* __restrict__ w_out) {
    const int i = blockIdx.x * 256 + threadIdx.x;
    const int total = (576 + 192) * CCH;
    if (i >= total) return;
    const float v = (i < 576 * CCH) ? w_qkv[i] : w_out[i - 576 * CCH];
    g_w16[i] = __float2half_rn(v);
}

// ============================================================================
// Transpose: x[b][192][HW] fp32 -> g_x16[b][pix][192] fp16
// ============================================================================
__global__ void transpose_k(const float* __restrict__ x) {
    __shared__ float tile[32][33];
    const int b  = blockIdx.z;
    const int p0 = blockIdx.x * 32, c0 = blockIdx.y * 32;
    const float* xb = x + (size_t)b * CCH * HW;
    __half* tb = g_x16 + (size_t)b * HW * CCH;
    const int tx = threadIdx.x, ty = threadIdx.y;
    #pragma unroll
    for (int j = 0; j < 32; j += 8)
        tile[ty + j][tx] = xb[(size_t)(c0 + ty + j) * HW + p0 + tx];
    __syncthreads();
    #pragma unroll
    for (int j = 0; j < 32; j += 8)
        tb[(size_t)(p0 + ty + j) * CCH + c0 + tx] = __float2half_rn(tile[tx][ty + j]);
}

// ============================================================================
// Wide-N pipelined fp16 GEMM: C[m][n] = sum_k A[m][k]*B[n][k]
//   Tile M=128, N=192, K staged 3x64 with cp.async double buffer.
//   512 threads = 16 warps (4x4), warp tile 32x48, acc 48 fp32 regs.
//   MODE=1: C fp32 [n][HW] channel-major (d_out); grid.x = 1.
//   MODE=2: qkv epilogue; grid.x = 3, blockIdx.x = type (0=q,1=k,2=v).
// ============================================================================
#define RS      144                     // smem tile row stride bytes
#define SM_BO   (128 * RS)              // B offset within buffer: 18432
#define BUFSZ   (SM_BO + 192 * RS)      // 46080 per stage buffer
#define SM_GTOT (2 * BUFSZ)             // 92160 (epilogue staging reuses it)

__device__ __forceinline__ void cp16(uint32_t dst, const void* src) {
    asm volatile("cp.async.cg.shared.global [%0], [%1], 16;"
                 :: "r"(dst), "l"(src));
}
#define CP_COMMIT() asm volatile("cp.async.commit_group;" ::: "memory")
#define CP_WAIT(n)  asm volatile("cp.async.wait_group %0;" :: "n"(n) : "memory")

__device__ __forceinline__ void mma16816(float* c, const uint32_t* a, const uint32_t* b) {
    asm volatile(
        "mma.sync.aligned.m16n8k16.row.col.f32.f16.f16.f32 "
        "{%0,%1,%2,%3}, {%4,%5,%6,%7}, {%8,%9}, {%0,%1,%2,%3};"
        : "+f"(c[0]), "+f"(c[1]), "+f"(c[2]), "+f"(c[3])
        : "r"(a[0]), "r"(a[1]), "r"(a[2]), "r"(a[3]), "r"(b[0]), "r"(b[1]));
}

template<int MODE>
__global__ __launch_bounds__(512, 1)
void mma_gemm(const __half* __restrict__ A, const __half* __restrict__ B,
              float* __restrict__ Cout)
{
    extern __shared__ char smem[];
    const uint32_t sb = (uint32_t)__cvta_generic_to_shared(smem);
    const int t    = threadIdx.x;
    const int wid  = t >> 5, lane = t & 31;
    const int gid  = lane >> 2, tig = lane & 3;
    const int wm   = wid & 3, wn = wid >> 2;
    const int m0   = blockIdx.y * 128;
    const int n0   = blockIdx.x * 192;
    const int b    = blockIdx.z;

    const __half* Ab = A + (size_t)b * HW * CCH + (size_t)m0 * CCH;

    float acc[2][6][4];
    #pragma unroll
    for (int mi = 0; mi < 2; mi++)
        #pragma unroll
        for (int ni = 0; ni < 6; ni++)
            #pragma unroll
            for (int j = 0; j < 4; j++) acc[mi][ni][j] = 0.f;

    // --- cp.async stage issue ------------------------------------------------
    auto issue_stage = [&](int s) {
        const int k0 = s * 64;
        const uint32_t base = sb + (s & 1) * BUFSZ;
        #pragma unroll
        for (int i = 0; i < 2; i++) {          // A: 128x64 fp16 = 1024 chunks
            const int idx = t + i * 512;
            const int row = idx >> 3, c8 = (idx & 7) * 8;
            cp16(base + row * RS + c8 * 2, Ab + (size_t)row * CCH + k0 + c8);
        }
        #pragma unroll
        for (int i = 0; i < 3; i++) {          // B: 192x64 fp16 = 1536 chunks
            const int idx = t + i * 512;
            const int row = idx >> 3, c8 = (idx & 7) * 8;
            cp16(base + SM_BO + row * RS + c8 * 2,
                 B + (size_t)(n0 + row) * CCH + k0 + c8);
        }
        CP_COMMIT();
    };

    issue_stage(0);

    #pragma unroll 1
    for (int s = 0; s < 3; s++) {
        if (s < 2) issue_stage(s + 1);
        if (s < 2) { CP_WAIT(1); } else { CP_WAIT(0); }
        __syncthreads();

        const char* cur = smem + (s & 1) * BUFSZ;
        #pragma unroll
        for (int kk = 0; kk < 4; kk++) {
            const uint32_t cb = kk * 32 + tig * 4;
            uint32_t ah[2][4], bh[6][2];
            #pragma unroll
            for (int mi = 0; mi < 2; mi++) {
                const uint32_t r0 = (wm * 32 + mi * 16 + gid) * RS + cb;
                ah[mi][0] = *(const uint32_t*)(cur + r0);
                ah[mi][1] = *(const uint32_t*)(cur + r0 + 8 * RS);
                ah[mi][2] = *(const uint32_t*)(cur + r0 + 16);
                ah[mi][3] = *(const uint32_t*)(cur + r0 + 8 * RS + 16);
            }
            #pragma unroll
            for (int ni = 0; ni < 6; ni++) {
                const uint32_t rn = (wn * 48 + ni * 8 + gid) * RS + cb;
                bh[ni][0] = *(const uint32_t*)(cur + SM_BO + rn);
                bh[ni][1] = *(const uint32_t*)(cur + SM_BO + rn + 16);
            }
            #pragma unroll
            for (int mi = 0; mi < 2; mi++)
                #pragma unroll
                for (int ni = 0; ni < 6; ni++)
                    mma16816(acc[mi][ni], ah[mi], bh[ni]);
        }
        __syncthreads();   // all warps done with this buffer before it's rewritten
    }

    if (MODE == 1) {
        // direct channel-major fp32 stores: Cout[b][col][HW]
        float* Cb = Cout + (size_t)b * CCH * HW;
        #pragma unroll
        for (int mi = 0; mi < 2; mi++) {
            const int row = m0 + wm * 32 + mi * 16 + gid;
            #pragma unroll
            for (int ni = 0; ni < 6; ni++) {
                const int col = n0 + wn * 48 + ni * 8 + 2 * tig;
                Cb[(size_t)col       * HW + row]     = acc[mi][ni][0];
                Cb[(size_t)(col + 1) * HW + row]     = acc[mi][ni][1];
                Cb[(size_t)col       * HW + row + 8] = acc[mi][ni][2];
                Cb[(size_t)(col + 1) * HW + row + 8] = acc[mi][ni][3];
            }
        }
    } else {
        // qkv epilogue: this CTA is entirely one type (blockIdx.x).
        const int type = blockIdx.x;            // 0=q, 1=k, 2=v
        const float sc = (type == 0) ? QSCALE : 1.0f;
        __half* st = (__half*)smem;             // stride 200 halves (400 B)
        #pragma unroll
        for (int mi = 0; mi < 2; mi++) {
            const int rl = wm * 32 + mi * 16 + gid;
            #pragma unroll
            for (int ni = 0; ni < 6; ni++) {
                const int cl = wn * 48 + ni * 8 + 2 * tig;
                *(__half2*)&st[rl * 200 + cl] =
                    __floats2half2_rn(acc[mi][ni][0] * sc, acc[mi][ni][1] * sc);
                *(__half2*)&st[(rl + 8) * 200 + cl] =
                    __floats2half2_rn(acc[mi][ni][2] * sc, acc[mi][ni][3] * sc);
            }
        }
        __syncthreads();
        __half* dst = (type == 0) ? g_q : (type == 1) ? g_k : g_v;
        #pragma unroll
        for (int i = 0; i < 6; i++) {           // 24 pgs x 128 rows = 3072 uint4
            const int idx = i * 512 + t;
            const int r = idx & 127, pg = idx >> 7;
            uint4 val = *(uint4*)&st[r * 200 + pg * 8];
            *(uint4*)&dst[(((size_t)b * 24 + pg) * HW + m0 + r) * 8] = val;
        }
    }
}

// ============================================================================
// Neighborhood attention (R12 banked: guarded body + exp2 + grouped fp16
// v-accum, promoted to fp32 once per window row).
// ============================================================================
template<int K, int DIL>
__device__ __forceinline__ void natt_body(const float* __restrict__ sbias,
                                          int head, int b)
{
    const int w   = blockIdx.x * 32 + threadIdx.x;
    const int h   = blockIdx.y * 4  + threadIdx.y;
    const int pix = h * IMG_W + w;

    const __half* qp = g_q + (((size_t)b * 24 + head * 4) * HW + pix) * 8;
    const __half* kb = g_k + ((size_t)b * 24 + head * 4) * HW * 8;
    const __half* vb = g_v + ((size_t)b * 24 + head * 4) * HW * 8;

    __half2 qh[16];
    #pragma unroll
    for (int j = 0; j < 4; j++) {
        uint4 r = *(const uint4*)(qp + (size_t)j * HW * 8);
        qh[4 * j + 0] = *(const __half2*)&r.x;
        qh[4 * j + 1] = *(const __half2*)&r.y;
        qh[4 * j + 2] = *(const __half2*)&r.z;
        qh[4 * j + 3] = *(const __half2*)&r.w;
    }

    float4 acc[8];
    #pragma unroll
    for (int i = 0; i < 8; i++) acc[i] = make_float4(0.f, 0.f, 0.f, 0.f);
    float l = 0.f;

    #pragma unroll 1
    for (int di = 0; di < K; di++) {
        const int hh = h + (di - K / 2) * DIL;
        const bool rok = ((unsigned)hh < IMG_H);

        __half2 a16[16];
        #pragma unroll
        for (int i = 0; i < 16; i++) a16[i] = __float2half2_rn(0.f);

        #pragma unroll
        for (int dj = 0; dj < K; dj++) {
            const int ww = w + (dj - K / 2) * DIL;
            const bool ok = rok && ((unsigned)ww < IMG_W);
            const int off = hh * IMG_W + ww;
            float s = 0.f;
            if (ok) {
                const __half* kp = kb + (size_t)off * 8;
                __half2 s0 = __float2half2_rn(0.f);
                __half2 s1 = __float2half2_rn(0.f);
                #pragma unroll
                for (int j = 0; j < 4; j++) {
                    uint4 raw = *(const uint4*)(kp + (size_t)j * HW * 8);
                    s0 = __hfma2(qh[4 * j + 0], *(const __half2*)&raw.x, s0);
                    s1 = __hfma2(qh[4 * j + 1], *(const __half2*)&raw.y, s1);
                    s0 = __hfma2(qh[4 * j + 2], *(const __half2*)&raw.z, s0);
                    s1 = __hfma2(qh[4 * j + 3], *(const __half2*)&raw.w, s1);
                }
                const float2 sf = __half22float2(__hadd2(s0, s1));
                s = sf.x + sf.y;
            }
            const float e = exp2f(s + sbias[di * K + dj]);
            l += e;
            if (ok) {
                const __half2 eh = __float2half2_rn(e);
                const __half* vp = vb + (size_t)off * 8;
                #pragma unroll
                for (int j = 0; j < 4; j++) {
                    uint4 raw = *(const uint4*)(vp + (size_t)j * HW * 8);
                    a16[4*j+0] = __hfma2(eh, *(const __half2*)&raw.x, a16[4*j+0]);
                    a16[4*j+1] = __hfma2(eh, *(const __half2*)&raw.y, a16[4*j+1]);
                    a16[4*j+2] = __hfma2(eh, *(const __half2*)&raw.z, a16[4*j+2]);
                    a16[4*j+3] = __hfma2(eh, *(const __half2*)&raw.w, a16[4*j+3]);
                }
            }
        }

        #pragma unroll
        for (int j = 0; j < 4; j++) {
            float2 f0 = __half22float2(a16[4*j+0]);
            float2 f1 = __half22float2(a16[4*j+1]);
            float2 f2 = __half22float2(a16[4*j+2]);
            float2 f3 = __half22float2(a16[4*j+3]);
            acc[2*j].x   += f0.x; acc[2*j].y   += f0.y;
            acc[2*j].z   += f1.x; acc[2*j].w   += f1.y;
            acc[2*j+1].x += f2.x; acc[2*j+1].y += f2.y;
            acc[2*j+1].z += f3.x; acc[2*j+1].w += f3.y;
        }
    }

    const float il = 1.f / l;
    const size_t ob = ((size_t)b * HW + pix) * CCH + head * 32;
    #pragma unroll
    for (int j = 0; j < 4; j++) {
        __half2 h0 = __floats2half2_rn(acc[2*j].x   * il, acc[2*j].y   * il);
        __half2 h1 = __floats2half2_rn(acc[2*j].z   * il, acc[2*j].w   * il);
        __half2 h2 = __floats2half2_rn(acc[2*j+1].x * il, acc[2*j+1].y * il);
        __half2 h3 = __floats2half2_rn(acc[2*j+1].z * il, acc[2*j+1].w * il);
        uint4 val;
        val.x = *(uint32_t*)&h0; val.y = *(uint32_t*)&h1;
        val.z = *(uint32_t*)&h2; val.w = *(uint32_t*)&h3;
        *(uint4*)&g_at[ob + j * 8] = val;
    }
}

__global__ __launch_bounds__(128, 6)
void natt_all(const float* __restrict__ b0, const float* __restrict__ b1,
              const float* __restrict__ b2, const float* __restrict__ b3,
              const float* __restrict__ b4, const float* __restrict__ b5)
{
    __shared__ float sb[81];
    // Heavy heads first: tail of the grid is cheap CTAs.
    const int HORD[6] = {4, 5, 3, 2, 1, 0};
    const int z = blockIdx.z;
    const int head = HORD[z >> 2];
    const int b    = z & 3;
    const float* bp;
    int k2;
    switch (head) {
        case 0: bp = b0; k2 = 9;  break;
        case 1: bp = b1; k2 = 25; break;
        case 2: bp = b2; k2 = 49; break;
        case 3: bp = b3; k2 = 49; break;
        case 4: bp = b4; k2 = 81; break;
        default: bp = b5; k2 = 81; break;
    }
    const int t = threadIdx.y * 32 + threadIdx.x;
    if (t < k2) sb[t] = bp[t] * INV_LN2;     // bias in log2 domain
    __syncthreads();
    switch (head) {
        case 0: natt_body<3, 1>(sb, 0, b); break;
        case 1: natt_body<5, 2>(sb, 1, b); break;
        case 2: natt_body<7, 1>(sb, 2, b); break;
        case 3: natt_body<7, 3>(sb, 3, b); break;
        case 4: natt_body<9, 1>(sb, 4, b); break;
        case 5: natt_body<9, 2>(sb, 5, b); break;
    }
}

// ============================================================================
extern "C" void kernel_launch(void* const* d_in, const int* in_sizes, int n_in,
                              void* d_out, int out_size)
{
    (void)in_sizes; (void)n_in; (void)out_size;
    const float* x     = (const float*)d_in[0];
    const float* w_qkv = (const float*)d_in[1];
    const float* w_out = (const float*)d_in[2];
    const float* b0 = (const float*)d_in[3];
    const float* b1 = (const float*)d_in[4];
    const float* b2 = (const float*)d_in[5];
    const float* b3 = (const float*)d_in[6];
    const float* b4 = (const float*)d_in[7];
    const float* b5 = (const float*)d_in[8];

    __half *x16, *w16, *at16;
    cudaGetSymbolAddress((void**)&x16,  g_x16);
    cudaGetSymbolAddress((void**)&w16,  g_w16);
    cudaGetSymbolAddress((void**)&at16, g_at);

    cudaFuncSetAttribute(mma_gemm<1>, cudaFuncAttributeMaxDynamicSharedMemorySize, SM_GTOT);
    cudaFuncSetAttribute(mma_gemm<2>, cudaFuncAttributeMaxDynamicSharedMemorySize, SM_GTOT);

    prep_weights<<<(768 * CCH + 255) / 256, 256>>>(w_qkv, w_out);
    transpose_k<<<dim3(HW / 32, CCH / 32, NB), dim3(32, 8)>>>(x);

    // qkv = x16 @ w_qkv^T  -> g_q / g_k / g_v (fp16 d8-packed, q pre-scaled)
    mma_gemm<2><<<dim3(3, HW / 128, NB), 512, SM_GTOT>>>(x16, w16, nullptr);

    natt_all<<<dim3(IMG_W / 32, IMG_H / 4, NB * 6), dim3(32, 4)>>>(
        b0, b1, b2, b3, b4, b5);

    // d_out[b][ch][pix] = (attn @ w_out^T)^T
    mma_gemm<1><<<dim3(1, HW / 128, NB), 512, SM_GTOT>>>(
        at16, w16 + 576 * CCH, (float*)d_out);
}